// round 13
// baseline (speedup 1.0000x reference)
#include <cuda_runtime.h>
#include <cuda_fp16.h>
#include <cstdint>
#include <math.h>

#define HW 4096
#define CPA_B 80                    // A smem row stride (bytes), 16B-aligned for ldmatrix
#define CPB_B 80                    // B smem row stride (bytes)
#define A_POS (4 * 66)              // halo positions per chunk tile
#define A_HALF_B (A_POS * CPA_B)    // bytes per hi/lo half (21120)
#define B_SLOT_B (128 * CPB_B)      // 10240 B per slot
#define NSLOT 6
#define SMEM_BYTES (128 + 2 * A_HALF_B + NSLOT * B_SLOT_B)   // 103808

// ---------------- device scratch ----------------
__device__ __half g_q_hi   [4u * 4096u * 768u];
__device__ __half g_q_lo   [4u * 4096u * 768u];
__device__ __half g_flat_hi[12u * 4096u * 256u];
__device__ __half g_flat_lo[12u * 4096u * 256u];
__device__ __half g_samp_hi[4u * 4096u * 256u];
__device__ __half g_samp_lo[4u * 4096u * 256u];
__device__ float g_value_t[12u * 4096u * 256u];
__device__ float g_oa_t   [4u * 4096u * 288u];        // merged off(0:192)+attn(192:288), token-major
__device__ float g_boa    [288];
__device__ __half g_wv [9u * 256u * 256u];
__device__ __half g_woa[9u * 288u * 768u];
__device__ __half g_wu [9u * 256u * 256u];

// ---------------- helpers ----------------
__device__ __forceinline__ void mma16816(float* c, const unsigned* a, unsigned b0, unsigned b1)
{
    asm volatile("mma.sync.aligned.m16n8k16.row.col.f32.f16.f16.f32 "
        "{%0,%1,%2,%3}, {%4,%5,%6,%7}, {%8,%9}, {%0,%1,%2,%3};"
        : "+f"(c[0]), "+f"(c[1]), "+f"(c[2]), "+f"(c[3])
        : "r"(a[0]), "r"(a[1]), "r"(a[2]), "r"(a[3]), "r"(b0), "r"(b1));
}

__device__ __forceinline__ void cp16(unsigned daddr, const void* src, int srcsz)
{
    asm volatile("cp.async.cg.shared.global [%0], [%1], 16, %2;\n"
                 :: "r"(daddr), "l"(src), "r"(srcsz));
}

__device__ __forceinline__ void ldsm4(unsigned* d, unsigned saddr)
{
    asm volatile("ldmatrix.sync.aligned.m8n8.x4.shared.b16 {%0,%1,%2,%3}, [%4];"
        : "=r"(d[0]), "=r"(d[1]), "=r"(d[2]), "=r"(d[3]) : "r"(saddr));
}

__device__ __forceinline__ void mbar_init(unsigned a, unsigned cnt)
{
    asm volatile("mbarrier.init.shared.b64 [%0], %1;" :: "r"(a), "r"(cnt) : "memory");
}

__device__ __forceinline__ void mbar_arrive(unsigned a)
{
    asm volatile("mbarrier.arrive.shared.b64 _, [%0];" :: "r"(a) : "memory");
}

__device__ __forceinline__ void mbar_wait(unsigned a, unsigned p)
{
    asm volatile(
        "{\n\t.reg .pred P1;\n\t"
        "WL_%=:\n\t"
        "mbarrier.try_wait.parity.acquire.cta.shared::cta.b64 P1, [%0], %1, 0x989680;\n\t"
        "@P1 bra.uni WD_%=;\n\t"
        "bra.uni WL_%=;\n\t"
        "WD_%=:\n\t}"
        :: "r"(a), "r"(p) : "memory");
}

// ---------------- conversion kernels ----------------
__global__ void chlast_split(const float* __restrict__ in, __half* __restrict__ hi,
                             __half* __restrict__ lo, int C)
{
    __shared__ float t[32][33];
    int img = blockIdx.z;
    int p0 = blockIdx.x * 32, c0 = blockIdx.y * 32;
    int tx = threadIdx.x;
    for (int j = threadIdx.y; j < 32; j += 8)
        t[j][tx] = in[((size_t)img * C + c0 + j) * HW + p0 + tx];
    __syncthreads();
    for (int j = threadIdx.y; j < 32; j += 8) {
        float v = t[tx][j];
        __half h = __float2half(v);
        size_t o = ((size_t)img * HW + p0 + j) * C + c0 + tx;
        hi[o] = h;
        lo[o] = __float2half(v - __half2float(h));
    }
}

__device__ __forceinline__ void wput(const float* __restrict__ w, __half* dst,
                                     int i, int cout, int cin, int co_off, int cout_buf)
{
    int ci = i % cin; int r = i / cin; int co = r % cout; int tap = r / cout;
    float v = w[((size_t)co * cin + ci) * 9 + tap];
    dst[((size_t)tap * cout_buf + co_off + co) * cin + ci] = __float2half(v);
}

#define WN0 (9 * 256 * 256)
#define WN1 (9 * 192 * 768)
#define WN2 (9 * 96  * 768)
#define WN3 (9 * 256 * 256)
__global__ void wprep(const float* __restrict__ wv, const float* __restrict__ wo,
                      const float* __restrict__ wa, const float* __restrict__ wu,
                      const float* __restrict__ bo, const float* __restrict__ ba)
{
    int i = blockIdx.x * 256 + threadIdx.x;
    if (i < WN0) wput(wv, g_wv, i, 256, 256, 0, 256);
    else if (i < WN0 + WN1) wput(wo, g_woa, i - WN0, 192, 768, 0, 288);
    else if (i < WN0 + WN1 + WN2) wput(wa, g_woa, i - WN0 - WN1, 96, 768, 192, 288);
    else if (i < WN0 + WN1 + WN2 + WN3) wput(wu, g_wu, i - WN0 - WN1 - WN2, 256, 256, 0, 256);
    else if (i < WN0 + WN1 + WN2 + WN3 + 288) {
        int j = i - (WN0 + WN1 + WN2 + WN3);
        g_boa[j] = j < 192 ? bo[j] : ba[j - 192];
    }
}

// ---------------- warp-specialized tensor-core implicit-GEMM 3x3 conv ----------------
// 288 threads: warps 0-7 compute (free-running, mbarrier-gated), warp 8 = producer.
// 6-slot B ring; single A buffer reused per chunk (one __syncthreads + a_full per chunk).
template<int CIN, int NTILE, bool TMAJOR>
__device__ __forceinline__ void conv_body(
         int bx, int by, int img,
         const __half* __restrict__ in_hi, const __half* __restrict__ in_lo,
         const __half* __restrict__ wt, const float* __restrict__ bias,
         float* __restrict__ out, int cout_total)
{
    extern __shared__ unsigned char smem_raw[];
    const unsigned sm_base = (unsigned)__cvta_generic_to_shared(smem_raw);
    const unsigned mb_afull = sm_base;            // 1 mbarrier
    const unsigned mb_full  = sm_base + 16;       // 6 mbarriers @ +16+8s
    const unsigned mb_empty = sm_base + 16 + 8 * NSLOT;
    const unsigned sA  = sm_base + 128;           // A hi then lo
    const unsigned sBb = sA + 2 * A_HALF_B;       // 6 slots

    const int tid = threadIdx.x;
    const int lane = tid & 31, wid = tid >> 5;

    constexpr int NA = NTILE / 16;
    constexpr int NWARP = NTILE / 2;
    constexpr int NCHUNK = CIN / 32;
    const int NTAP = NCHUNK * 9;

    const int Nbase = by * NTILE;
    const int y0    = bx * 2;

    if (tid == 0) {
        mbar_init(mb_afull, 1);
        #pragma unroll
        for (int s = 0; s < NSLOT; s++) {
            mbar_init(mb_full + 8 * s, 1);
            mbar_init(mb_empty + 8 * s, 8);
        }
    }
    // first chunk's __syncthreads publishes the inits

    if (wid == 8) {
        // ---------------- producer ----------------
        int g_next = 0;
        int pslot = 0, pphase = 1;      // empty cursor (phase 1: first waits pass)
        #pragma unroll 1
        for (int c = 0; c < NCHUNK; c++) {
            __syncthreads();            // all A(c-1) reads done
            // stage A(c)
            const int cb = c * 32;
            #pragma unroll 1
            for (int i = lane; i < A_POS * 8; i += 32) {
                int pos = i >> 3, sub = i & 7;
                int hf = sub >> 2, seg = sub & 3;
                int ry = pos / 66, col = pos % 66;
                int gy = y0 - 1 + ry, gx = col - 1;
                int ok = ((unsigned)gy < 64u && (unsigned)gx < 64u) ? 16 : 0;
                int gyc = gy < 0 ? 0 : (gy > 63 ? 63 : gy);
                int gxc = gx < 0 ? 0 : (gx > 63 ? 63 : gx);
                const __half* src = (hf ? in_lo : in_hi)
                    + ((size_t)(img * HW + gyc * 64 + gxc)) * CIN + cb + seg * 8;
                cp16(sA + (unsigned)(hf * A_HALF_B + pos * CPA_B + seg * 16), src, ok);
            }
            asm volatile("cp.async.commit_group;\n" ::);
            asm volatile("cp.async.wait_group 0;\n" ::);
            if (lane == 0) mbar_arrive(mb_afull);
            // stage B slabs through 2 taps into the next chunk
            int lim = (c + 1) * 9 + 2; if (lim > NTAP) lim = NTAP;
            #pragma unroll 1
            for (; g_next < lim; g_next++) {
                mbar_wait(mb_empty + 8 * pslot, (unsigned)pphase);
                int cbb = (g_next / 9) * 32;
                int tp  = g_next % 9;
                const unsigned slotb = sBb + (unsigned)(pslot * B_SLOT_B);
                #pragma unroll 1
                for (int i = lane; i < NTILE * 4; i += 32) {
                    int n = i >> 2, seg = i & 3;
                    size_t gsrc = ((size_t)(tp * cout_total + Nbase + n)) * CIN + cbb + seg * 8;
                    cp16(slotb + (unsigned)(n * CPB_B + seg * 16), wt + gsrc, 16);
                }
                asm volatile("cp.async.commit_group;\n" ::);
                asm volatile("cp.async.wait_group 0;\n" ::);
                if (lane == 0) mbar_arrive(mb_full + 8 * pslot);
                if (++pslot == NSLOT) { pslot = 0; pphase ^= 1; }
            }
        }
        return;   // producer skips epilogue
    }

    // ---------------- consumers (warps 0-7) ----------------
    const int jj = lane >> 3, rr = lane & 7;
    const int gid = lane >> 2, tig = lane & 3;
    const int warpM = wid & 3, warpN = wid >> 2;
    const int Mbase = bx * 128;

    float acc[2][NA][4];
    #pragma unroll
    for (int ma = 0; ma < 2; ma++)
        #pragma unroll
        for (int na = 0; na < NA; na++)
            #pragma unroll
            for (int q = 0; q < 4; q++) acc[ma][na][q] = 0.f;

    int cslot = 0, cphase = 0;   // full cursor
    int aphase = 0;
    #pragma unroll 1
    for (int c = 0; c < NCHUNK; c++) {
        __syncthreads();
        mbar_wait(mb_afull, (unsigned)aphase); aphase ^= 1;
        #pragma unroll 1
        for (int tap = 0; tap < 9; tap++) {
            mbar_wait(mb_full + 8 * cslot, (unsigned)cphase);

            const int dy = tap / 3, dx = tap - dy * 3;
            const unsigned slotb = sBb + (unsigned)(cslot * B_SLOT_B);

            unsigned ra_h[2][2][4], ra_l[2][2][4], rb[2][NA / 2][4];
            #pragma unroll
            for (int ks = 0; ks < 2; ks++) {
                const int kb2 = ks * 32;
                #pragma unroll
                for (int ma = 0; ma < 2; ma++) {
                    int pixel = warpM * 32 + ma * 16 + ((jj & 1) << 3) + rr;
                    int yy = (pixel >> 6) + dy;
                    int xx = (pixel & 63) + dx;
                    unsigned aofs = (unsigned)((yy * 66 + xx) * CPA_B + kb2 + ((jj >> 1) << 4));
                    ldsm4(ra_h[ks][ma], sA + aofs);
                    ldsm4(ra_l[ks][ma], sA + A_HALF_B + aofs);
                }
                #pragma unroll
                for (int np = 0; np < NA / 2; np++) {
                    int n = warpN * NWARP + (np * 2 + (jj >> 1)) * 8 + rr;
                    unsigned bofs = (unsigned)(n * CPB_B + kb2 + ((jj & 1) << 4));
                    ldsm4(rb[ks][np], slotb + bofs);
                }
            }
            if (lane == 0) mbar_arrive(mb_empty + 8 * cslot);
            if (++cslot == NSLOT) { cslot = 0; cphase ^= 1; }

            #pragma unroll
            for (int ks = 0; ks < 2; ks++)
                #pragma unroll
                for (int np = 0; np < NA / 2; np++)
                    #pragma unroll
                    for (int ma = 0; ma < 2; ma++) {
                        mma16816(acc[ma][np * 2],     ra_h[ks][ma], rb[ks][np][0], rb[ks][np][1]);
                        mma16816(acc[ma][np * 2],     ra_l[ks][ma], rb[ks][np][0], rb[ks][np][1]);
                        mma16816(acc[ma][np * 2 + 1], ra_h[ks][ma], rb[ks][np][2], rb[ks][np][3]);
                        mma16816(acc[ma][np * 2 + 1], ra_l[ks][ma], rb[ks][np][2], rb[ks][np][3]);
                    }
        }
    }

    // ---- epilogue ----
    #pragma unroll
    for (int ma = 0; ma < 2; ma++) {
        int pix = Mbase + warpM * 32 + ma * 16 + gid;
        #pragma unroll
        for (int na = 0; na < NA; na++) {
            int co = Nbase + warpN * NWARP + na * 8 + tig * 2;
            float bv0 = bias[co], bv1 = bias[co + 1];
            if (TMAJOR) {
                float2* p0 = reinterpret_cast<float2*>(out + ((size_t)img * HW + pix) * cout_total + co);
                float2* p1 = reinterpret_cast<float2*>(out + ((size_t)img * HW + pix + 8) * cout_total + co);
                *p0 = make_float2(acc[ma][na][0] + bv0, acc[ma][na][1] + bv1);
                *p1 = make_float2(acc[ma][na][2] + bv0, acc[ma][na][3] + bv1);
            } else {
                out[((size_t)img * cout_total + co)     * HW + pix]     = acc[ma][na][0] + bv0;
                out[((size_t)img * cout_total + co + 1) * HW + pix]     = acc[ma][na][1] + bv1;
                out[((size_t)img * cout_total + co)     * HW + pix + 8] = acc[ma][na][2] + bv0;
                out[((size_t)img * cout_total + co + 1) * HW + pix + 8] = acc[ma][na][3] + bv1;
            }
        }
    }
}

__global__ void __launch_bounds__(288, 1)
conv_pair(const float* __restrict__ b_value)
{
    int bxg = blockIdx.x;
    if (bxg < 384) {
        int x = bxg & 31, y = (bxg >> 5) % 3, img = bxg / 96;
        conv_body<768, 96, true>(x, y, img, g_q_hi, g_q_lo, g_woa, g_boa, g_oa_t, 288);
    } else {
        int t = bxg - 384;
        int x = t & 31, y = (t >> 5) & 1, img = t >> 6;
        conv_body<256, 128, true>(x, y, img, g_flat_hi, g_flat_lo, g_wv, b_value, g_value_t, 256);
    }
}

__global__ void __launch_bounds__(288, 1)
conv_out(const float* __restrict__ b_out, float* __restrict__ out)
{
    conv_body<256, 128, false>(blockIdx.x, blockIdx.y, blockIdx.z,
                               g_samp_hi, g_samp_lo, g_wu, b_out, out, 256);
}

// ---------------- MSDA: lane-parallel softmax + bilinear setup ------------------
__global__ __launch_bounds__(256)
void msda_kernel(const float* __restrict__ refp)
{
    const unsigned FULL = 0xFFFFFFFFu;
    int gw = blockIdx.x * 8 + (threadIdx.x >> 5);
    int lane = threadIdx.x & 31;
    int head = gw & 7;
    int pix  = (gw >> 3) & 4095;
    int b    = gw >> 15;

    size_t tok = (size_t)b * HW + pix;
    const float* op = g_oa_t + tok * 288;

    float lg = (lane < 12) ? op[192 + head * 12 + lane] : -1e30f;
    float mx = lg;
    #pragma unroll
    for (int s = 16; s > 0; s >>= 1) mx = fmaxf(mx, __shfl_xor_sync(FULL, mx, s));
    float e = (lane < 12) ? __expf(lg - mx) : 0.f;
    float den = e;
    #pragma unroll
    for (int s = 16; s > 0; s >>= 1) den += __shfl_xor_sync(FULL, den, s);
    float aw = e / den;

    float offv = (lane < 24) ? op[head * 24 + lane] : 0.f;
    float refv = (lane < 6) ? refp[tok * 6 + lane] : 0.f;

    int lsel = (lane >> 2) * 2;
    float rx = __shfl_sync(FULL, refv, lsel);
    float ry = __shfl_sync(FULL, refv, lsel + 1);
    float ox = __shfl_sync(FULL, offv, lane * 2 < 32 ? lane * 2 : 0);
    float oy = __shfl_sync(FULL, offv, lane * 2 + 1 < 32 ? lane * 2 + 1 : 0);
    float xf = rx * 64.f + ox - 0.5f;
    float yf = ry * 64.f + oy - 0.5f;
    float x0f = floorf(xf), y0f = floorf(yf);
    int x0 = (int)x0f, y0 = (int)y0f;
    float lx = xf - x0f, ly = yf - y0f;
    float w00 = (1.f - lx) * (1.f - ly) * aw;
    float w10 = lx * (1.f - ly) * aw;
    float w01 = (1.f - lx) * ly * aw;
    float w11 = lx * ly * aw;
    bool vx0 = (unsigned)x0 < 64u, vx1 = (unsigned)(x0 + 1) < 64u;
    bool vy0 = (unsigned)y0 < 64u, vy1 = (unsigned)(y0 + 1) < 64u;
    w00 = (vx0 && vy0) ? w00 : 0.f;
    w10 = (vx1 && vy0) ? w10 : 0.f;
    w01 = (vx0 && vy1) ? w01 : 0.f;
    w11 = (vx1 && vy1) ? w11 : 0.f;
    int xc0 = min(max(x0, 0), 63), xc1 = min(max(x0 + 1, 0), 63);
    int yc0 = min(max(y0, 0), 63), yc1 = min(max(y0 + 1, 0), 63);
    int i00 = yc0 * 64 + xc0, i10 = yc0 * 64 + xc1;
    int i01 = yc1 * 64 + xc0, i11 = yc1 * 64 + xc1;

    const float* vb0 = g_value_t + ((size_t)(b * 3 + 0) * HW) * 256 + head * 32 + lane;
    const float* vb1 = vb0 + (size_t)HW * 256;
    const float* vb2 = vb1 + (size_t)HW * 256;

    float acc = 0.f;
    #pragma unroll
    for (int j = 0; j < 12; j++) {
        const float* vb = (j < 4) ? vb0 : (j < 8 ? vb1 : vb2);
        float u00 = __shfl_sync(FULL, w00, j);
        float u10 = __shfl_sync(FULL, w10, j);
        float u01 = __shfl_sync(FULL, w01, j);
        float u11 = __shfl_sync(FULL, w11, j);
        int   k00 = __shfl_sync(FULL, i00, j);
        int   k10 = __shfl_sync(FULL, i10, j);
        int   k01 = __shfl_sync(FULL, i01, j);
        int   k11 = __shfl_sync(FULL, i11, j);
        if (u00 != 0.f) acc += u00 * vb[(size_t)k00 * 256];
        if (u10 != 0.f) acc += u10 * vb[(size_t)k10 * 256];
        if (u01 != 0.f) acc += u01 * vb[(size_t)k01 * 256];
        if (u11 != 0.f) acc += u11 * vb[(size_t)k11 * 256];
    }

    __half h = __float2half(acc);
    size_t o = tok * 256 + head * 32 + lane;
    g_samp_hi[o] = h;
    g_samp_lo[o] = __float2half(acc - __half2float(h));
}

// ---------------- launcher ----------------------------------------------------------
extern "C" void kernel_launch(void* const* d_in, const int* in_sizes, int n_in,
                              void* d_out, int out_size)
{
    const float* query   = (const float*)d_in[0];
    const float* refp    = (const float*)d_in[1];
    const float* flat    = (const float*)d_in[2];
    const float* w_value = (const float*)d_in[6];
    const float* b_value = (const float*)d_in[7];
    const float* w_off   = (const float*)d_in[8];
    const float* b_off   = (const float*)d_in[9];
    const float* w_attn  = (const float*)d_in[10];
    const float* b_attn  = (const float*)d_in[11];
    const float* w_out   = (const float*)d_in[12];
    const float* b_out   = (const float*)d_in[13];

    __half *q_hi, *q_lo, *f_hi, *f_lo;
    cudaGetSymbolAddress((void**)&q_hi, g_q_hi);
    cudaGetSymbolAddress((void**)&q_lo, g_q_lo);
    cudaGetSymbolAddress((void**)&f_hi, g_flat_hi);
    cudaGetSymbolAddress((void**)&f_lo, g_flat_lo);

    cudaFuncSetAttribute(conv_pair, cudaFuncAttributeMaxDynamicSharedMemorySize, SMEM_BYTES);
    cudaFuncSetAttribute(conv_out,  cudaFuncAttributeMaxDynamicSharedMemorySize, SMEM_BYTES);

    chlast_split<<<dim3(128, 8, 12), dim3(32, 8)>>>(flat, f_hi, f_lo, 256);
    chlast_split<<<dim3(128, 24, 4), dim3(32, 8)>>>(query, q_hi, q_lo, 768);
    wprep<<<(WN0 + WN1 + WN2 + WN3 + 288 + 255) / 256, 256>>>(w_value, w_off, w_attn, w_out, b_off, b_attn);

    // launch 3 (ncu window): warp-specialized merged convs
    conv_pair<<<1152, 288, SMEM_BYTES>>>(b_value);

    // launch 4: deformable attention sampling
    msda_kernel<<<(4 * HW * 8) / 8, 256>>>(refp);

    // launch 5: output conv -> NCHW d_out
    conv_out<<<dim3(32, 2, 4), 288, SMEM_BYTES>>>(b_out, (float*)d_out);
}

// round 15
// speedup vs baseline: 1.6951x; 1.6951x over previous
#include <cuda_runtime.h>
#include <cuda_fp16.h>
#include <cstdint>
#include <math.h>

#define HW 4096
#define CPA_B 80                    // A smem row stride (bytes), 16B-aligned for ldmatrix
#define CPB_B 80                    // B smem row stride (bytes)
#define A_POS (4 * 66)              // halo positions per chunk tile
#define A_HALF_B (A_POS * CPA_B)    // bytes per hi/lo half (21120)
#define B_SLOT_B (128 * CPB_B)      // 10240 B per slab
#define TRIP_B (3 * B_SLOT_B)       // 30720 B per triple-slot (3 dx slabs)
#define SMEM_BYTES (2 * A_HALF_B + 2 * TRIP_B)   // 103680 -> 2 CTAs/SM

// ---------------- device scratch ----------------
__device__ __half g_q_hi   [4u * 4096u * 768u];
__device__ __half g_q_lo   [4u * 4096u * 768u];
__device__ __half g_flat_hi[12u * 4096u * 256u];
__device__ __half g_flat_lo[12u * 4096u * 256u];
__device__ __half g_samp_hi[4u * 4096u * 256u];
__device__ __half g_samp_lo[4u * 4096u * 256u];
__device__ float g_value_t[12u * 4096u * 256u];
__device__ float g_oa_t   [4u * 4096u * 288u];        // merged off(0:192)+attn(192:288), token-major
__device__ float g_boa    [288];
__device__ __half g_wv [9u * 256u * 256u];
__device__ __half g_woa[9u * 288u * 768u];
__device__ __half g_wu [9u * 256u * 256u];

// ---------------- helpers ----------------
__device__ __forceinline__ void mma16816(float* c, const unsigned* a, unsigned b0, unsigned b1)
{
    asm volatile("mma.sync.aligned.m16n8k16.row.col.f32.f16.f16.f32 "
        "{%0,%1,%2,%3}, {%4,%5,%6,%7}, {%8,%9}, {%0,%1,%2,%3};"
        : "+f"(c[0]), "+f"(c[1]), "+f"(c[2]), "+f"(c[3])
        : "r"(a[0]), "r"(a[1]), "r"(a[2]), "r"(a[3]), "r"(b0), "r"(b1));
}

__device__ __forceinline__ void cp16(unsigned daddr, const void* src, int srcsz)
{
    asm volatile("cp.async.cg.shared.global [%0], [%1], 16, %2;\n"
                 :: "r"(daddr), "l"(src), "r"(srcsz));
}

__device__ __forceinline__ void ldsm4(unsigned* d, unsigned saddr)
{
    asm volatile("ldmatrix.sync.aligned.m8n8.x4.shared.b16 {%0,%1,%2,%3}, [%4];"
        : "=r"(d[0]), "=r"(d[1]), "=r"(d[2]), "=r"(d[3]) : "r"(saddr));
}

// ---------------- conversion kernels ----------------
__global__ void chlast_split(const float* __restrict__ in, __half* __restrict__ hi,
                             __half* __restrict__ lo, int C)
{
    __shared__ float t[32][33];
    int img = blockIdx.z;
    int p0 = blockIdx.x * 32, c0 = blockIdx.y * 32;
    int tx = threadIdx.x;
    for (int j = threadIdx.y; j < 32; j += 8)
        t[j][tx] = in[((size_t)img * C + c0 + j) * HW + p0 + tx];
    __syncthreads();
    for (int j = threadIdx.y; j < 32; j += 8) {
        float v = t[tx][j];
        __half h = __float2half(v);
        size_t o = ((size_t)img * HW + p0 + j) * C + c0 + tx;
        hi[o] = h;
        lo[o] = __float2half(v - __half2float(h));
    }
}

// w[co][ci][3][3] fp32 -> buf[tap][co_off+co][ci] fp16 (single, no split)
__device__ __forceinline__ void wput(const float* __restrict__ w, __half* dst,
                                     int i, int cout, int cin, int co_off, int cout_buf)
{
    int ci = i % cin; int r = i / cin; int co = r % cout; int tap = r / cout;
    float v = w[((size_t)co * cin + ci) * 9 + tap];
    dst[((size_t)tap * cout_buf + co_off + co) * cin + ci] = __float2half(v);
}

#define WN0 (9 * 256 * 256)
#define WN1 (9 * 192 * 768)
#define WN2 (9 * 96  * 768)
#define WN3 (9 * 256 * 256)
__global__ void wprep(const float* __restrict__ wv, const float* __restrict__ wo,
                      const float* __restrict__ wa, const float* __restrict__ wu,
                      const float* __restrict__ bo, const float* __restrict__ ba)
{
    int i = blockIdx.x * 256 + threadIdx.x;
    if (i < WN0) wput(wv, g_wv, i, 256, 256, 0, 256);
    else if (i < WN0 + WN1) wput(wo, g_woa, i - WN0, 192, 768, 0, 288);
    else if (i < WN0 + WN1 + WN2) wput(wa, g_woa, i - WN0 - WN1, 96, 768, 192, 288);
    else if (i < WN0 + WN1 + WN2 + WN3) wput(wu, g_wu, i - WN0 - WN1 - WN2, 256, 256, 0, 256);
    else if (i < WN0 + WN1 + WN2 + WN3 + 288) {
        int j = i - (WN0 + WN1 + WN2 + WN3);
        g_boa[j] = j < 192 ? bo[j] : ba[j - 192];
    }
}

// ---------------- tensor-core implicit-GEMM 3x3 conv body ----------------
// fp16 2-term. Taps grouped in dy-triplets: ONE wait+sync per 3 taps.
// 2 triple-slots (ring), prefetch distance 1; A single-buffered per chunk.
template<int CIN, int NTILE, bool TMAJOR>
__device__ __forceinline__ void conv_body(
         int bx, int by, int img,
         const __half* __restrict__ in_hi, const __half* __restrict__ in_lo,
         const __half* __restrict__ wt, const float* __restrict__ bias,
         float* __restrict__ out, int cout_total)
{
    extern __shared__ unsigned char smem_raw[];
    const unsigned sm_base = (unsigned)__cvta_generic_to_shared(smem_raw);
    const unsigned sA  = sm_base;                     // A hi then lo
    const unsigned sBb = sm_base + 2 * A_HALF_B;      // 2 triple-slots

    const int tid = threadIdx.x;
    const int lane = tid & 31, warp = tid >> 5;
    const int gid = lane >> 2, tig = lane & 3;
    const int jj = lane >> 3, rr = lane & 7;
    const int warpM = warp & 3, warpN = warp >> 2;

    constexpr int NA = NTILE / 16;
    constexpr int NWARP = NTILE / 2;
    constexpr int NCHUNK = CIN / 32;
    constexpr int NTRIP = NCHUNK * 3;

    const int Mbase = bx * 128;
    const int Nbase = by * NTILE;
    const int y0    = bx * 2;

    float acc[2][NA][4];
    #pragma unroll
    for (int ma = 0; ma < 2; ma++)
        #pragma unroll
        for (int na = 0; na < NA; na++)
            #pragma unroll
            for (int q = 0; q < 4; q++) acc[ma][na][q] = 0.f;

    // stage triple-slot for triplet T (chunk T/3, dy=T%3, dx=0..2), one commit group
    auto issue_trip = [&](int T) {
        if (T < NTRIP) {
            const int c = T / 3, t = T - c * 3;
            const int cbb = c * 32;
            const unsigned base = sBb + (unsigned)((T & 1) * TRIP_B);
            #pragma unroll
            for (int dx = 0; dx < 3; dx++) {
                const int tp = t * 3 + dx;
                const unsigned slotb = base + (unsigned)(dx * B_SLOT_B);
                #pragma unroll 1
                for (int i = tid; i < NTILE * 4; i += 256) {
                    int n = i >> 2, seg = i & 3;
                    size_t gsrc = ((size_t)(tp * cout_total + Nbase + n)) * CIN + cbb + seg * 8;
                    cp16(slotb + (unsigned)(n * CPB_B + seg * 16), wt + gsrc, 16);
                }
            }
            asm volatile("cp.async.commit_group;\n" ::);
        }
    };

    issue_trip(0);

    int T = 0;
    #pragma unroll 1
    for (int cb = 0; cb < CIN; cb += 32) {
        __syncthreads();   // all ldsm reads of A(prev chunk) complete

        // stage A halo for this chunk (own commit group)
        #pragma unroll 1
        for (int i = tid; i < A_POS * 8; i += 256) {
            int pos = i >> 3, sub = i & 7;
            int hf = sub >> 2, seg = sub & 3;
            int ry = pos / 66, col = pos % 66;
            int gy = y0 - 1 + ry, gx = col - 1;
            int ok = ((unsigned)gy < 64u && (unsigned)gx < 64u) ? 16 : 0;
            int gyc = gy < 0 ? 0 : (gy > 63 ? 63 : gy);
            int gxc = gx < 0 ? 0 : (gx > 63 ? 63 : gx);
            const __half* src = (hf ? in_lo : in_hi)
                + ((size_t)(img * HW + gyc * 64 + gxc)) * CIN + cb + seg * 8;
            cp16(sA + (unsigned)(hf * A_HALF_B + pos * CPA_B + seg * 16), src, ok);
        }
        asm volatile("cp.async.commit_group;\n" ::);

        #pragma unroll 1
        for (int t = 0; t < 3; t++, T++) {
            asm volatile("cp.async.wait_group 0;\n" ::);   // T(cur) (+A at t=0) done
            __syncthreads();                               // cross-thread visibility
            issue_trip(T + 1);                             // slot (T+1)&1 free since T-1's sync

            const int dy = t;
            const unsigned base = sBb + (unsigned)((T & 1) * TRIP_B);

            #pragma unroll
            for (int dx = 0; dx < 3; dx++) {
                const unsigned slotb = base + (unsigned)(dx * B_SLOT_B);
                #pragma unroll
                for (int ks = 0; ks < 2; ks++) {
                    const int kb2 = ks * 32;
                    unsigned ra_h[2][4], ra_l[2][4];
                    #pragma unroll
                    for (int ma = 0; ma < 2; ma++) {
                        int pixel = warpM * 32 + ma * 16 + ((jj & 1) << 3) + rr;
                        int yy = (pixel >> 6) + dy;
                        int xx = (pixel & 63) + dx;
                        unsigned aofs = (unsigned)((yy * 66 + xx) * CPA_B + kb2 + ((jj >> 1) << 4));
                        ldsm4(ra_h[ma], sA + aofs);
                        ldsm4(ra_l[ma], sA + A_HALF_B + aofs);
                    }
                    #pragma unroll
                    for (int np = 0; np < NA / 2; np++) {
                        int n = warpN * NWARP + (np * 2 + (jj >> 1)) * 8 + rr;
                        unsigned bofs = (unsigned)(n * CPB_B + kb2 + ((jj & 1) << 4));
                        unsigned rbh[4];
                        ldsm4(rbh, slotb + bofs);
                        #pragma unroll
                        for (int ma = 0; ma < 2; ma++) {
                            mma16816(acc[ma][np * 2],     ra_h[ma], rbh[0], rbh[1]);
                            mma16816(acc[ma][np * 2],     ra_l[ma], rbh[0], rbh[1]);
                            mma16816(acc[ma][np * 2 + 1], ra_h[ma], rbh[2], rbh[3]);
                            mma16816(acc[ma][np * 2 + 1], ra_l[ma], rbh[2], rbh[3]);
                        }
                    }
                }
            }
        }
    }

    #pragma unroll
    for (int ma = 0; ma < 2; ma++) {
        int pix = Mbase + warpM * 32 + ma * 16 + gid;
        #pragma unroll
        for (int na = 0; na < NA; na++) {
            int co = Nbase + warpN * NWARP + na * 8 + tig * 2;
            float bv0 = bias[co], bv1 = bias[co + 1];
            if (TMAJOR) {
                float2* p0 = reinterpret_cast<float2*>(out + ((size_t)img * HW + pix) * cout_total + co);
                float2* p1 = reinterpret_cast<float2*>(out + ((size_t)img * HW + pix + 8) * cout_total + co);
                *p0 = make_float2(acc[ma][na][0] + bv0, acc[ma][na][1] + bv1);
                *p1 = make_float2(acc[ma][na][2] + bv0, acc[ma][na][3] + bv1);
            } else {
                out[((size_t)img * cout_total + co)     * HW + pix]     = acc[ma][na][0] + bv0;
                out[((size_t)img * cout_total + co + 1) * HW + pix]     = acc[ma][na][1] + bv1;
                out[((size_t)img * cout_total + co)     * HW + pix + 8] = acc[ma][na][2] + bv0;
                out[((size_t)img * cout_total + co + 1) * HW + pix + 8] = acc[ma][na][3] + bv1;
            }
        }
    }
}

__global__ void __launch_bounds__(256, 2)
conv_pair(const float* __restrict__ b_value)
{
    int bxg = blockIdx.x;
    if (bxg < 384) {
        int x = bxg & 31, y = (bxg >> 5) % 3, img = bxg / 96;
        conv_body<768, 96, true>(x, y, img, g_q_hi, g_q_lo, g_woa, g_boa, g_oa_t, 288);
    } else {
        int t = bxg - 384;
        int x = t & 31, y = (t >> 5) & 1, img = t >> 6;
        conv_body<256, 128, true>(x, y, img, g_flat_hi, g_flat_lo, g_wv, b_value, g_value_t, 256);
    }
}

__global__ void __launch_bounds__(256, 2)
conv_out(const float* __restrict__ b_out, float* __restrict__ out)
{
    conv_body<256, 128, false>(blockIdx.x, blockIdx.y, blockIdx.z,
                               g_samp_hi, g_samp_lo, g_wu, b_out, out, 256);
}

// ---------------- MSDA: lane-parallel softmax + bilinear setup ------------------
__global__ __launch_bounds__(256)
void msda_kernel(const float* __restrict__ refp)
{
    const unsigned FULL = 0xFFFFFFFFu;
    int gw = blockIdx.x * 8 + (threadIdx.x >> 5);
    int lane = threadIdx.x & 31;
    int head = gw & 7;
    int pix  = (gw >> 3) & 4095;
    int b    = gw >> 15;

    size_t tok = (size_t)b * HW + pix;
    const float* op = g_oa_t + tok * 288;

    float lg = (lane < 12) ? op[192 + head * 12 + lane] : -1e30f;
    float mx = lg;
    #pragma unroll
    for (int s = 16; s > 0; s >>= 1) mx = fmaxf(mx, __shfl_xor_sync(FULL, mx, s));
    float e = (lane < 12) ? __expf(lg - mx) : 0.f;
    float den = e;
    #pragma unroll
    for (int s = 16; s > 0; s >>= 1) den += __shfl_xor_sync(FULL, den, s);
    float aw = e / den;

    float offv = (lane < 24) ? op[head * 24 + lane] : 0.f;
    float refv = (lane < 6) ? refp[tok * 6 + lane] : 0.f;

    int lsel = (lane >> 2) * 2;
    float rx = __shfl_sync(FULL, refv, lsel);
    float ry = __shfl_sync(FULL, refv, lsel + 1);
    float ox = __shfl_sync(FULL, offv, lane * 2 < 32 ? lane * 2 : 0);
    float oy = __shfl_sync(FULL, offv, lane * 2 + 1 < 32 ? lane * 2 + 1 : 0);
    float xf = rx * 64.f + ox - 0.5f;
    float yf = ry * 64.f + oy - 0.5f;
    float x0f = floorf(xf), y0f = floorf(yf);
    int x0 = (int)x0f, y0 = (int)y0f;
    float lx = xf - x0f, ly = yf - y0f;
    float w00 = (1.f - lx) * (1.f - ly) * aw;
    float w10 = lx * (1.f - ly) * aw;
    float w01 = (1.f - lx) * ly * aw;
    float w11 = lx * ly * aw;
    bool vx0 = (unsigned)x0 < 64u, vx1 = (unsigned)(x0 + 1) < 64u;
    bool vy0 = (unsigned)y0 < 64u, vy1 = (unsigned)(y0 + 1) < 64u;
    w00 = (vx0 && vy0) ? w00 : 0.f;
    w10 = (vx1 && vy0) ? w10 : 0.f;
    w01 = (vx0 && vy1) ? w01 : 0.f;
    w11 = (vx1 && vy1) ? w11 : 0.f;
    int xc0 = min(max(x0, 0), 63), xc1 = min(max(x0 + 1, 0), 63);
    int yc0 = min(max(y0, 0), 63), yc1 = min(max(y0 + 1, 0), 63);
    int i00 = yc0 * 64 + xc0, i10 = yc0 * 64 + xc1;
    int i01 = yc1 * 64 + xc0, i11 = yc1 * 64 + xc1;

    const float* vb0 = g_value_t + ((size_t)(b * 3 + 0) * HW) * 256 + head * 32 + lane;
    const float* vb1 = vb0 + (size_t)HW * 256;
    const float* vb2 = vb1 + (size_t)HW * 256;

    float acc = 0.f;
    #pragma unroll
    for (int j = 0; j < 12; j++) {
        const float* vb = (j < 4) ? vb0 : (j < 8 ? vb1 : vb2);
        float u00 = __shfl_sync(FULL, w00, j);
        float u10 = __shfl_sync(FULL, w10, j);
        float u01 = __shfl_sync(FULL, w01, j);
        float u11 = __shfl_sync(FULL, w11, j);
        int   k00 = __shfl_sync(FULL, i00, j);
        int   k10 = __shfl_sync(FULL, i10, j);
        int   k01 = __shfl_sync(FULL, i01, j);
        int   k11 = __shfl_sync(FULL, i11, j);
        if (u00 != 0.f) acc += u00 * vb[(size_t)k00 * 256];
        if (u10 != 0.f) acc += u10 * vb[(size_t)k10 * 256];
        if (u01 != 0.f) acc += u01 * vb[(size_t)k01 * 256];
        if (u11 != 0.f) acc += u11 * vb[(size_t)k11 * 256];
    }

    __half h = __float2half(acc);
    size_t o = tok * 256 + head * 32 + lane;
    g_samp_hi[o] = h;
    g_samp_lo[o] = __float2half(acc - __half2float(h));
}

// ---------------- launcher ----------------------------------------------------------
extern "C" void kernel_launch(void* const* d_in, const int* in_sizes, int n_in,
                              void* d_out, int out_size)
{
    const float* query   = (const float*)d_in[0];
    const float* refp    = (const float*)d_in[1];
    const float* flat    = (const float*)d_in[2];
    const float* w_value = (const float*)d_in[6];
    const float* b_value = (const float*)d_in[7];
    const float* w_off   = (const float*)d_in[8];
    const float* b_off   = (const float*)d_in[9];
    const float* w_attn  = (const float*)d_in[10];
    const float* b_attn  = (const float*)d_in[11];
    const float* w_out   = (const float*)d_in[12];
    const float* b_out   = (const float*)d_in[13];

    __half *q_hi, *q_lo, *f_hi, *f_lo;
    cudaGetSymbolAddress((void**)&q_hi, g_q_hi);
    cudaGetSymbolAddress((void**)&q_lo, g_q_lo);
    cudaGetSymbolAddress((void**)&f_hi, g_flat_hi);
    cudaGetSymbolAddress((void**)&f_lo, g_flat_lo);

    cudaFuncSetAttribute(conv_pair, cudaFuncAttributeMaxDynamicSharedMemorySize, SMEM_BYTES);
    cudaFuncSetAttribute(conv_out,  cudaFuncAttributeMaxDynamicSharedMemorySize, SMEM_BYTES);

    chlast_split<<<dim3(128, 8, 12), dim3(32, 8)>>>(flat, f_hi, f_lo, 256);
    chlast_split<<<dim3(128, 24, 4), dim3(32, 8)>>>(query, q_hi, q_lo, 768);
    wprep<<<(WN0 + WN1 + WN2 + WN3 + 288 + 255) / 256, 256>>>(w_value, w_off, w_attn, w_out, b_off, b_attn);

    // launch 3 (ncu window): merged convs, dy-triplet sync epochs
    conv_pair<<<1152, 256, SMEM_BYTES>>>(b_value);

    // launch 4: deformable attention sampling
    msda_kernel<<<(4 * HW * 8) / 8, 256>>>(refp);

    // launch 5: output conv -> NCHW d_out
    conv_out<<<dim3(32, 2, 4), 256, SMEM_BYTES>>>(b_out, (float*)d_out);
}

// round 16
// speedup vs baseline: 1.7236x; 1.0168x over previous
#include <cuda_runtime.h>
#include <cuda_fp16.h>
#include <cstdint>
#include <math.h>

#define HW 4096
#define CPA_B 80                    // A smem row stride (bytes), 16B-aligned for ldmatrix
#define CPB_B 80                    // B smem row stride (bytes)
#define A_POS (4 * 66)              // halo positions per chunk tile (4 rows x 66)
#define A_HALF_B (A_POS * CPA_B)    // bytes per hi/lo half (21120)
#define B_SLOT_B (128 * CPB_B)      // 10240 B per slab
#define TRIP_B (3 * B_SLOT_B)       // 30720 B per triple-slot (3 dx slabs)
#define SMEM_BYTES (2 * A_HALF_B + 2 * TRIP_B)   // 103680 -> 2 CTAs/SM

// ---------------- device scratch ----------------
__device__ __half g_q_hi   [4u * 4096u * 768u];
__device__ __half g_q_lo   [4u * 4096u * 768u];
__device__ __half g_flat_hi[12u * 4096u * 256u];
__device__ __half g_flat_lo[12u * 4096u * 256u];
__device__ __half g_samp_hi[4u * 4096u * 256u];
__device__ __half g_samp_lo[4u * 4096u * 256u];
__device__ float g_value_t[12u * 4096u * 256u];
__device__ float g_oa_t   [4u * 4096u * 288u];        // merged off(0:192)+attn(192:288), token-major
__device__ float g_boa    [288];
__device__ __half g_wv [9u * 256u * 256u];
__device__ __half g_woa[9u * 288u * 768u];
__device__ __half g_wu [9u * 256u * 256u];

// ---------------- helpers ----------------
__device__ __forceinline__ void mma16816(float* c, const unsigned* a, unsigned b0, unsigned b1)
{
    asm volatile("mma.sync.aligned.m16n8k16.row.col.f32.f16.f16.f32 "
        "{%0,%1,%2,%3}, {%4,%5,%6,%7}, {%8,%9}, {%0,%1,%2,%3};"
        : "+f"(c[0]), "+f"(c[1]), "+f"(c[2]), "+f"(c[3])
        : "r"(a[0]), "r"(a[1]), "r"(a[2]), "r"(a[3]), "r"(b0), "r"(b1));
}

__device__ __forceinline__ void cp16(unsigned daddr, const void* src, int srcsz)
{
    asm volatile("cp.async.cg.shared.global [%0], [%1], 16, %2;\n"
                 :: "r"(daddr), "l"(src), "r"(srcsz));
}

__device__ __forceinline__ void ldsm4(unsigned* d, unsigned saddr)
{
    asm volatile("ldmatrix.sync.aligned.m8n8.x4.shared.b16 {%0,%1,%2,%3}, [%4];"
        : "=r"(d[0]), "=r"(d[1]), "=r"(d[2]), "=r"(d[3]) : "r"(saddr));
}

// ---------------- conversion kernels ----------------
__global__ void chlast_split(const float* __restrict__ in, __half* __restrict__ hi,
                             __half* __restrict__ lo, int C)
{
    __shared__ float t[32][33];
    int img = blockIdx.z;
    int p0 = blockIdx.x * 32, c0 = blockIdx.y * 32;
    int tx = threadIdx.x;
    for (int j = threadIdx.y; j < 32; j += 8)
        t[j][tx] = in[((size_t)img * C + c0 + j) * HW + p0 + tx];
    __syncthreads();
    for (int j = threadIdx.y; j < 32; j += 8) {
        float v = t[tx][j];
        __half h = __float2half(v);
        size_t o = ((size_t)img * HW + p0 + j) * C + c0 + tx;
        hi[o] = h;
        lo[o] = __float2half(v - __half2float(h));
    }
}

// w[co][ci][3][3] fp32 -> buf[tap][co_off+co][ci] fp16 (single, no split)
__device__ __forceinline__ void wput(const float* __restrict__ w, __half* dst,
                                     int i, int cout, int cin, int co_off, int cout_buf)
{
    int ci = i % cin; int r = i / cin; int co = r % cout; int tap = r / cout;
    float v = w[((size_t)co * cin + ci) * 9 + tap];
    dst[((size_t)tap * cout_buf + co_off + co) * cin + ci] = __float2half(v);
}

#define WN0 (9 * 256 * 256)
#define WN1 (9 * 192 * 768)
#define WN2 (9 * 96  * 768)
#define WN3 (9 * 256 * 256)
__global__ void wprep(const float* __restrict__ wv, const float* __restrict__ wo,
                      const float* __restrict__ wa, const float* __restrict__ wu,
                      const float* __restrict__ bo, const float* __restrict__ ba)
{
    int i = blockIdx.x * 256 + threadIdx.x;
    if (i < WN0) wput(wv, g_wv, i, 256, 256, 0, 256);
    else if (i < WN0 + WN1) wput(wo, g_woa, i - WN0, 192, 768, 0, 288);
    else if (i < WN0 + WN1 + WN2) wput(wa, g_woa, i - WN0 - WN1, 96, 768, 192, 288);
    else if (i < WN0 + WN1 + WN2 + WN3) wput(wu, g_wu, i - WN0 - WN1 - WN2, 256, 256, 0, 256);
    else if (i < WN0 + WN1 + WN2 + WN3 + 288) {
        int j = i - (WN0 + WN1 + WN2 + WN3);
        g_boa[j] = j < 192 ? bo[j] : ba[j - 192];
    }
}

// ---------------- tensor-core implicit-GEMM 3x3 conv body ----------------
// fp16 2-term. dy-triplet epochs (one wait+sync per 3 taps). A is row-pipelined:
// triplet t reads A tile-rows [t, t+1], so rows 0-1 of chunk c+1 are staged during
// (c,2) and rows 2-3 during (c+1,0) -- A load fully overlapped, no double buffer.
template<int CIN, int NTILE, bool TMAJOR>
__device__ __forceinline__ void conv_body(
         int bx, int by, int img,
         const __half* __restrict__ in_hi, const __half* __restrict__ in_lo,
         const __half* __restrict__ wt, const float* __restrict__ bias,
         float* __restrict__ out, int cout_total)
{
    extern __shared__ unsigned char smem_raw[];
    const unsigned sm_base = (unsigned)__cvta_generic_to_shared(smem_raw);
    const unsigned sA  = sm_base;                     // A hi then lo
    const unsigned sBb = sm_base + 2 * A_HALF_B;      // 2 triple-slots

    const int tid = threadIdx.x;
    const int lane = tid & 31, warp = tid >> 5;
    const int gid = lane >> 2, tig = lane & 3;
    const int jj = lane >> 3, rr = lane & 7;
    const int warpM = warp & 3, warpN = warp >> 2;

    constexpr int NA = NTILE / 16;
    constexpr int NWARP = NTILE / 2;
    constexpr int NCHUNK = CIN / 32;
    constexpr int NTRIP = NCHUNK * 3;

    const int Mbase = bx * 128;
    const int Nbase = by * NTILE;
    const int y0    = bx * 2;

    float acc[2][NA][4];
    #pragma unroll
    for (int ma = 0; ma < 2; ma++)
        #pragma unroll
        for (int na = 0; na < NA; na++)
            #pragma unroll
            for (int q = 0; q < 4; q++) acc[ma][na][q] = 0.f;

    // stage A tile-rows [half*2, half*2+1] (132 positions) for chunk c (no commit)
    auto stage_a_piece = [&](int c, int half) {
        const int cb = c * 32;
        #pragma unroll 1
        for (int i = tid; i < 132 * 8; i += 256) {
            int pos = (i >> 3) + half * 132;
            int sub = i & 7;
            int hf = sub >> 2, seg = sub & 3;
            int ry = pos / 66, col = pos % 66;
            int gy = y0 - 1 + ry, gx = col - 1;
            int ok = ((unsigned)gy < 64u && (unsigned)gx < 64u) ? 16 : 0;
            int gyc = gy < 0 ? 0 : (gy > 63 ? 63 : gy);
            int gxc = gx < 0 ? 0 : (gx > 63 ? 63 : gx);
            const __half* src = (hf ? in_lo : in_hi)
                + ((size_t)(img * HW + gyc * 64 + gxc)) * CIN + cb + seg * 8;
            cp16(sA + (unsigned)(hf * A_HALF_B + pos * CPA_B + seg * 16), src, ok);
        }
    };

    // stage triple-slot for triplet T (chunk T/3, dy=T%3, dx=0..2) -- no commit
    auto issue_trip = [&](int T) {
        if (T < NTRIP) {
            const int c = T / 3, t = T - c * 3;
            const int cbb = c * 32;
            const unsigned base = sBb + (unsigned)((T & 1) * TRIP_B);
            #pragma unroll
            for (int dx = 0; dx < 3; dx++) {
                const int tp = t * 3 + dx;
                const unsigned slotb = base + (unsigned)(dx * B_SLOT_B);
                #pragma unroll 1
                for (int i = tid; i < NTILE * 4; i += 256) {
                    int n = i >> 2, seg = i & 3;
                    size_t gsrc = ((size_t)(tp * cout_total + Nbase + n)) * CIN + cbb + seg * 8;
                    cp16(slotb + (unsigned)(n * CPB_B + seg * 16), wt + gsrc, 16);
                }
            }
        }
    };

    // bootstrap: full A(0) + trip(0) in one group
    stage_a_piece(0, 0);
    stage_a_piece(0, 1);
    issue_trip(0);
    asm volatile("cp.async.commit_group;\n" ::);

    int T = 0;
    #pragma unroll 1
    for (int c = 0; c < NCHUNK; c++) {
        #pragma unroll 1
        for (int t = 0; t < 3; t++, T++) {
            asm volatile("cp.async.wait_group 0;\n" ::);   // trip(T) + A pieces ready
            __syncthreads();                               // visibility + WAR ordering

            // one commit group per triplet: next B trip + scheduled A piece
            issue_trip(T + 1);
            if (t == 2 && c + 1 < NCHUNK) stage_a_piece(c + 1, 0);  // rows 0-1 of next chunk
            if (t == 0 && c > 0)          stage_a_piece(c, 1);      // rows 2-3 of this chunk
            asm volatile("cp.async.commit_group;\n" ::);

            const int dy = t;
            const unsigned base = sBb + (unsigned)((T & 1) * TRIP_B);

            #pragma unroll
            for (int dx = 0; dx < 3; dx++) {
                const unsigned slotb = base + (unsigned)(dx * B_SLOT_B);
                #pragma unroll
                for (int ks = 0; ks < 2; ks++) {
                    const int kb2 = ks * 32;
                    unsigned ra_h[2][4], ra_l[2][4];
                    #pragma unroll
                    for (int ma = 0; ma < 2; ma++) {
                        int pixel = warpM * 32 + ma * 16 + ((jj & 1) << 3) + rr;
                        int yy = (pixel >> 6) + dy;
                        int xx = (pixel & 63) + dx;
                        unsigned aofs = (unsigned)((yy * 66 + xx) * CPA_B + kb2 + ((jj >> 1) << 4));
                        ldsm4(ra_h[ma], sA + aofs);
                        ldsm4(ra_l[ma], sA + A_HALF_B + aofs);
                    }
                    #pragma unroll
                    for (int np = 0; np < NA / 2; np++) {
                        int n = warpN * NWARP + (np * 2 + (jj >> 1)) * 8 + rr;
                        unsigned bofs = (unsigned)(n * CPB_B + kb2 + ((jj & 1) << 4));
                        unsigned rbh[4];
                        ldsm4(rbh, slotb + bofs);
                        #pragma unroll
                        for (int ma = 0; ma < 2; ma++) {
                            mma16816(acc[ma][np * 2],     ra_h[ma], rbh[0], rbh[1]);
                            mma16816(acc[ma][np * 2],     ra_l[ma], rbh[0], rbh[1]);
                            mma16816(acc[ma][np * 2 + 1], ra_h[ma], rbh[2], rbh[3]);
                            mma16816(acc[ma][np * 2 + 1], ra_l[ma], rbh[2], rbh[3]);
                        }
                    }
                }
            }
        }
    }

    #pragma unroll
    for (int ma = 0; ma < 2; ma++) {
        int pix = Mbase + warpM * 32 + ma * 16 + gid;
        #pragma unroll
        for (int na = 0; na < NA; na++) {
            int co = Nbase + warpN * NWARP + na * 8 + tig * 2;
            float bv0 = bias[co], bv1 = bias[co + 1];
            if (TMAJOR) {
                float2* p0 = reinterpret_cast<float2*>(out + ((size_t)img * HW + pix) * cout_total + co);
                float2* p1 = reinterpret_cast<float2*>(out + ((size_t)img * HW + pix + 8) * cout_total + co);
                *p0 = make_float2(acc[ma][na][0] + bv0, acc[ma][na][1] + bv1);
                *p1 = make_float2(acc[ma][na][2] + bv0, acc[ma][na][3] + bv1);
            } else {
                out[((size_t)img * cout_total + co)     * HW + pix]     = acc[ma][na][0] + bv0;
                out[((size_t)img * cout_total + co + 1) * HW + pix]     = acc[ma][na][1] + bv1;
                out[((size_t)img * cout_total + co)     * HW + pix + 8] = acc[ma][na][2] + bv0;
                out[((size_t)img * cout_total + co + 1) * HW + pix + 8] = acc[ma][na][3] + bv1;
            }
        }
    }
}

__global__ void __launch_bounds__(256, 2)
conv_pair(const float* __restrict__ b_value)
{
    int bxg = blockIdx.x;
    if (bxg < 384) {
        int x = bxg & 31, y = (bxg >> 5) % 3, img = bxg / 96;
        conv_body<768, 96, true>(x, y, img, g_q_hi, g_q_lo, g_woa, g_boa, g_oa_t, 288);
    } else {
        int t = bxg - 384;
        int x = t & 31, y = (t >> 5) & 1, img = t >> 6;
        conv_body<256, 128, true>(x, y, img, g_flat_hi, g_flat_lo, g_wv, b_value, g_value_t, 256);
    }
}

__global__ void __launch_bounds__(256, 2)
conv_out(const float* __restrict__ b_out, float* __restrict__ out)
{
    conv_body<256, 128, false>(blockIdx.x, blockIdx.y, blockIdx.z,
                               g_samp_hi, g_samp_lo, g_wu, b_out, out, 256);
}

// ---------------- MSDA: lane-parallel softmax + bilinear setup ------------------
__global__ __launch_bounds__(256)
void msda_kernel(const float* __restrict__ refp)
{
    const unsigned FULL = 0xFFFFFFFFu;
    int gw = blockIdx.x * 8 + (threadIdx.x >> 5);
    int lane = threadIdx.x & 31;
    int head = gw & 7;
    int pix  = (gw >> 3) & 4095;
    int b    = gw >> 15;

    size_t tok = (size_t)b * HW + pix;
    const float* op = g_oa_t + tok * 288;

    float lg = (lane < 12) ? op[192 + head * 12 + lane] : -1e30f;
    float mx = lg;
    #pragma unroll
    for (int s = 16; s > 0; s >>= 1) mx = fmaxf(mx, __shfl_xor_sync(FULL, mx, s));
    float e = (lane < 12) ? __expf(lg - mx) : 0.f;
    float den = e;
    #pragma unroll
    for (int s = 16; s > 0; s >>= 1) den += __shfl_xor_sync(FULL, den, s);
    float aw = e / den;

    float offv = (lane < 24) ? op[head * 24 + lane] : 0.f;
    float refv = (lane < 6) ? refp[tok * 6 + lane] : 0.f;

    int lsel = (lane >> 2) * 2;
    float rx = __shfl_sync(FULL, refv, lsel);
    float ry = __shfl_sync(FULL, refv, lsel + 1);
    float ox = __shfl_sync(FULL, offv, lane * 2 < 32 ? lane * 2 : 0);
    float oy = __shfl_sync(FULL, offv, lane * 2 + 1 < 32 ? lane * 2 + 1 : 0);
    float xf = rx * 64.f + ox - 0.5f;
    float yf = ry * 64.f + oy - 0.5f;
    float x0f = floorf(xf), y0f = floorf(yf);
    int x0 = (int)x0f, y0 = (int)y0f;
    float lx = xf - x0f, ly = yf - y0f;
    float w00 = (1.f - lx) * (1.f - ly) * aw;
    float w10 = lx * (1.f - ly) * aw;
    float w01 = (1.f - lx) * ly * aw;
    float w11 = lx * ly * aw;
    bool vx0 = (unsigned)x0 < 64u, vx1 = (unsigned)(x0 + 1) < 64u;
    bool vy0 = (unsigned)y0 < 64u, vy1 = (unsigned)(y0 + 1) < 64u;
    w00 = (vx0 && vy0) ? w00 : 0.f;
    w10 = (vx1 && vy0) ? w10 : 0.f;
    w01 = (vx0 && vy1) ? w01 : 0.f;
    w11 = (vx1 && vy1) ? w11 : 0.f;
    int xc0 = min(max(x0, 0), 63), xc1 = min(max(x0 + 1, 0), 63);
    int yc0 = min(max(y0, 0), 63), yc1 = min(max(y0 + 1, 0), 63);
    int i00 = yc0 * 64 + xc0, i10 = yc0 * 64 + xc1;
    int i01 = yc1 * 64 + xc0, i11 = yc1 * 64 + xc1;

    const float* vb0 = g_value_t + ((size_t)(b * 3 + 0) * HW) * 256 + head * 32 + lane;
    const float* vb1 = vb0 + (size_t)HW * 256;
    const float* vb2 = vb1 + (size_t)HW * 256;

    float acc = 0.f;
    #pragma unroll
    for (int j = 0; j < 12; j++) {
        const float* vb = (j < 4) ? vb0 : (j < 8 ? vb1 : vb2);
        float u00 = __shfl_sync(FULL, w00, j);
        float u10 = __shfl_sync(FULL, w10, j);
        float u01 = __shfl_sync(FULL, w01, j);
        float u11 = __shfl_sync(FULL, w11, j);
        int   k00 = __shfl_sync(FULL, i00, j);
        int   k10 = __shfl_sync(FULL, i10, j);
        int   k01 = __shfl_sync(FULL, i01, j);
        int   k11 = __shfl_sync(FULL, i11, j);
        if (u00 != 0.f) acc += u00 * vb[(size_t)k00 * 256];
        if (u10 != 0.f) acc += u10 * vb[(size_t)k10 * 256];
        if (u01 != 0.f) acc += u01 * vb[(size_t)k01 * 256];
        if (u11 != 0.f) acc += u11 * vb[(size_t)k11 * 256];
    }

    __half h = __float2half(acc);
    size_t o = tok * 256 + head * 32 + lane;
    g_samp_hi[o] = h;
    g_samp_lo[o] = __float2half(acc - __half2float(h));
}

// ---------------- launcher ----------------------------------------------------------
extern "C" void kernel_launch(void* const* d_in, const int* in_sizes, int n_in,
                              void* d_out, int out_size)
{
    const float* query   = (const float*)d_in[0];
    const float* refp    = (const float*)d_in[1];
    const float* flat    = (const float*)d_in[2];
    const float* w_value = (const float*)d_in[6];
    const float* b_value = (const float*)d_in[7];
    const float* w_off   = (const float*)d_in[8];
    const float* b_off   = (const float*)d_in[9];
    const float* w_attn  = (const float*)d_in[10];
    const float* b_attn  = (const float*)d_in[11];
    const float* w_out   = (const float*)d_in[12];
    const float* b_out   = (const float*)d_in[13];

    __half *q_hi, *q_lo, *f_hi, *f_lo;
    cudaGetSymbolAddress((void**)&q_hi, g_q_hi);
    cudaGetSymbolAddress((void**)&q_lo, g_q_lo);
    cudaGetSymbolAddress((void**)&f_hi, g_flat_hi);
    cudaGetSymbolAddress((void**)&f_lo, g_flat_lo);

    cudaFuncSetAttribute(conv_pair, cudaFuncAttributeMaxDynamicSharedMemorySize, SMEM_BYTES);
    cudaFuncSetAttribute(conv_out,  cudaFuncAttributeMaxDynamicSharedMemorySize, SMEM_BYTES);

    chlast_split<<<dim3(128, 8, 12), dim3(32, 8)>>>(flat, f_hi, f_lo, 256);
    chlast_split<<<dim3(128, 24, 4), dim3(32, 8)>>>(query, q_hi, q_lo, 768);
    wprep<<<(WN0 + WN1 + WN2 + WN3 + 288 + 255) / 256, 256>>>(w_value, w_off, w_attn, w_out, b_off, b_attn);

    // launch 3 (ncu window): merged convs, triplet epochs + A row pipelining
    conv_pair<<<1152, 256, SMEM_BYTES>>>(b_value);

    // launch 4: deformable attention sampling
    msda_kernel<<<(4 * HW * 8) / 8, 256>>>(refp);

    // launch 5: output conv -> NCHW d_out
    conv_out<<<dim3(32, 2, 4), 256, SMEM_BYTES>>>(b_out, (float*)d_out);
}